// round 14
// baseline (speedup 1.0000x reference)
#include <cuda_runtime.h>
#include <cstdint>

// Rodrigues rotation matrix from two vectors.
// R13 structure (best ncu): TPB=256, 2 elems/thread block-strided,
// 512 elems/block, single reused 18KB smem buffer, register-staged smem
// reads, 6 CTAs/SM; streaming (.cs) output stores; __fdividef; sqrt-free
// degenerate test (sqrtf(s2) < 1e-30 <=> s2 == 0 in fp32).
// Phase-1 input fill now uses cp.async.cg (LDGSTS.128) with evict_last
// L2 hint: GMEM->SMEM without the register round-trip.

#define TPB 256
#define EPB 512                       // elements per block
#define IN_WORDS (EPB * 3)            // 1536 floats per input
#define OUT_WORDS (EPB * 9)           // 4608 floats = 18 KB
#define IN_F4 (IN_WORDS / 4)          // 384 f4 per input
#define OUT_F4 (OUT_WORDS / 4)        // 1152 f4

#define RTOL_ 1e-5f
#define ATOL_ 1e-8f

__device__ __forceinline__ void stg_streaming(float4* p, float4 v) {
    asm volatile("st.global.cs.v4.f32 [%0], {%1,%2,%3,%4};"
                 :: "l"(p), "f"(v.x), "f"(v.y), "f"(v.z), "f"(v.w) : "memory");
}

__global__ __launch_bounds__(TPB, 6) void rodrigues_kernel(
    const float4* __restrict__ g1,
    const float4* __restrict__ g2,
    float4* __restrict__ gout)
{
    __shared__ float sbuf[OUT_WORDS];             // 18 KB, reused in+out
    float4* sb4 = (float4*)sbuf;

    const int tid = threadIdx.x;
    const int blk = blockIdx.x;

    uint64_t pol;
    asm volatile("createpolicy.fractional.L2::evict_last.b64 %0, 1.0;" : "=l"(pol));

    // ---- Phase 1: cp.async.cg GMEM->SMEM (no register round-trip) ----
    const float4* in1 = g1 + (size_t)blk * IN_F4;
    const float4* in2 = g2 + (size_t)blk * IN_F4;
#pragma unroll
    for (int j = 0; j < 3; j++) {
        int i = j * TPB + tid;
        const float4* src = (i < IN_F4) ? (in1 + i) : (in2 + (i - IN_F4));
        uint32_t saddr = (uint32_t)__cvta_generic_to_shared(sb4 + i);
        asm volatile(
            "cp.async.cg.shared.global.L2::cache_hint [%0], [%1], 16, %2;"
            :: "r"(saddr), "l"(src), "l"(pol) : "memory");
    }
    asm volatile("cp.async.commit_group;" ::: "memory");
    asm volatile("cp.async.wait_group 0;" ::: "memory");
    __syncthreads();

    // ---- Phase 2: stride-3 scalar LDS (conflict-free) into regs ----
    float A[6], Bv[6];
#pragma unroll
    for (int k = 0; k < 2; k++) {
        int m = k * TPB + tid;
#pragma unroll
        for (int c = 0; c < 3; c++) {
            A[3 * k + c]  = sbuf[3 * m + c];
            Bv[3 * k + c] = sbuf[IN_WORDS + 3 * m + c];
        }
    }
    __syncthreads();   // inputs now in regs; sbuf becomes output buffer

    // ---- Phase 3: compute, immediate stride-9 scalar STS (conflict-free) ----
#pragma unroll
    for (int k = 0; k < 2; k++) {
        float ax = A[3 * k + 0], ay = A[3 * k + 1], az = A[3 * k + 2];
        float bx = Bv[3 * k + 0], by = Bv[3 * k + 1], bz = Bv[3 * k + 2];

        float ra = rsqrtf(ax * ax + ay * ay + az * az);
        ax *= ra; ay *= ra; az *= ra;
        float rb = rsqrtf(bx * bx + by * by + bz * bz);
        bx *= rb; by *= rb; bz *= rb;

        // v = a x b
        float vx = ay * bz - az * by;
        float vy = az * bx - ax * bz;
        float vz = ax * by - ay * bx;
        float c  = ax * bx + ay * by + az * bz;
        float s2 = vx * vx + vy * vy + vz * vz;

        // coef = (1-c)/s2_safe (fast approx division; rel-err budget 1e-3)
        float coef = __fdividef(1.0f - c, (s2 > 0.0f ? s2 : 1.0f));

        // R = I + K + (v v^T - s2 I) * coef
        float r00 = 1.0f + (vx * vx - s2) * coef;
        float r01 = vx * vy * coef - vz;
        float r02 = vx * vz * coef + vy;
        float r10 = vx * vy * coef + vz;
        float r11 = 1.0f + (vy * vy - s2) * coef;
        float r12 = vy * vz * coef - vx;
        float r20 = vx * vz * coef - vy;
        float r21 = vy * vz * coef + vx;
        float r22 = 1.0f + (vz * vz - s2) * coef;

        // sqrtf(s2) < 1e-30  <=>  s2 == 0 in fp32
        if (s2 == 0.0f) {
            if (c > 0.0f) {
                r00 = 1.0f; r01 = 0.0f; r02 = 0.0f;
                r10 = 0.0f; r11 = 1.0f; r12 = 0.0f;
                r20 = 0.0f; r21 = 0.0f; r22 = 1.0f;
            } else if (c < 0.0f) {
                bool close_e1 = (fabsf(ax - 1.0f) <= ATOL_ + RTOL_) &&
                                (fabsf(ay) <= ATOL_) &&
                                (fabsf(az) <= ATOL_);
                float ex = close_e1 ? 0.0f : 1.0f;
                float ey = close_e1 ? 1.0f : 0.0f;
                float px = -az * ey;
                float py =  az * ex;
                float pz = ax * ey - ay * ex;
                float pn = sqrtf(px * px + py * py + pz * pz);
                float inv = (pn > 0.0f) ? (1.0f / pn) : 1.0f;
                px *= inv; py *= inv; pz *= inv;
                r00 = 2.0f * px * px - 1.0f;
                r01 = 2.0f * px * py;
                r02 = 2.0f * px * pz;
                r10 = 2.0f * py * px;
                r11 = 2.0f * py * py - 1.0f;
                r12 = 2.0f * py * pz;
                r20 = 2.0f * pz * px;
                r21 = 2.0f * pz * py;
                r22 = 2.0f * pz * pz - 1.0f;
            }
        }

        float* o = sbuf + 9 * (k * TPB + tid);
        o[0] = r00; o[1] = r01; o[2] = r02;
        o[3] = r10; o[4] = r11; o[5] = r12;
        o[6] = r20; o[7] = r21; o[8] = r22;
    }
    __syncthreads();

    // ---- Phase 4: coalesced streaming stores (evict-first) ----
    float4* dst = gout + (size_t)blk * OUT_F4;
#pragma unroll
    for (int j = 0; j < 4; j++)
        stg_streaming(dst + j * TPB + tid, sb4[j * TPB + tid]);
    if (tid < OUT_F4 - 4 * TPB)                      // 128, warp-uniform
        stg_streaming(dst + 4 * TPB + tid, sb4[4 * TPB + tid]);
}

extern "C" void kernel_launch(void* const* d_in, const int* in_sizes, int n_in,
                              void* d_out, int out_size)
{
    const float4* v1 = (const float4*)d_in[0];
    const float4* v2 = (const float4*)d_in[1];
    float4* out = (float4*)d_out;

    int n_elems = in_sizes[0] / 3;        // 4,194,304
    int blocks = n_elems / EPB;           // 8192 (exact)

    rodrigues_kernel<<<blocks, TPB>>>(v1, v2, out);
}

// round 15
// speedup vs baseline: 1.2363x; 1.2363x over previous
#include <cuda_runtime.h>
#include <cstdint>

// Rodrigues rotation matrix from two vectors — roofline-final kernel.
// TPB=256, 2 elems/thread (block-strided), 512 elems/block, 6 CTAs/SM.
// Single reused 18KB smem buffer:
//   coalesced f4 GMEM loads (L2 evict_last hint) -> smem
//   conflict-free stride-3 scalar LDS -> registers
//   compute (Rodrigues via v v^T - s2 I identity; no 3x3 matmul)
//   conflict-free stride-9 scalar STS
//   coalesced streaming (.cs) f4 stores.
// App traffic 252MB @ ~37us = ~6.8TB/s — at the HBM3e mixed r/w roof.

#define S_EPS 1e-30f
#define RTOL_ 1e-5f
#define ATOL_ 1e-8f

#define TPB 256
#define EPB 512                       // elements per block
#define IN_WORDS (EPB * 3)            // 1536 floats per input
#define OUT_WORDS (EPB * 9)           // 4608 floats = 18 KB
#define IN_F4 (IN_WORDS / 4)          // 384 f4 per input
#define OUT_F4 (OUT_WORDS / 4)        // 1152 f4

__device__ __forceinline__ float4 ldg_evict_last(const float4* p, uint64_t pol) {
    float4 v;
    asm volatile("ld.global.nc.L2::cache_hint.v4.f32 {%0,%1,%2,%3}, [%4], %5;"
                 : "=f"(v.x), "=f"(v.y), "=f"(v.z), "=f"(v.w)
                 : "l"(p), "l"(pol));
    return v;
}

__device__ __forceinline__ void stg_streaming(float4* p, float4 v) {
    asm volatile("st.global.cs.v4.f32 [%0], {%1,%2,%3,%4};"
                 :: "l"(p), "f"(v.x), "f"(v.y), "f"(v.z), "f"(v.w) : "memory");
}

__global__ __launch_bounds__(TPB, 6) void rodrigues_kernel(
    const float4* __restrict__ g1,
    const float4* __restrict__ g2,
    float4* __restrict__ gout)
{
    __shared__ float sbuf[OUT_WORDS];             // 18 KB, reused in+out
    float4* sb4 = (float4*)sbuf;

    const int tid = threadIdx.x;
    const int blk = blockIdx.x;

    uint64_t pol;
    asm volatile("createpolicy.fractional.L2::evict_last.b64 %0, 1.0;" : "=l"(pol));

    // ---- Phase 1: coalesced f4 loads with evict_last L2 policy ----
    const float4* s1 = g1 + (size_t)blk * IN_F4;
    const float4* s2 = g2 + (size_t)blk * IN_F4;
#pragma unroll
    for (int j = 0; j < 3; j++) {
        int i = j * TPB + tid;
        sb4[i] = (i < IN_F4) ? ldg_evict_last(s1 + i, pol)
                             : ldg_evict_last(s2 + (i - IN_F4), pol);
    }
    __syncthreads();

    // ---- Phase 2: stride-3 scalar LDS (conflict-free) into regs ----
    float A[6], Bv[6];
#pragma unroll
    for (int k = 0; k < 2; k++) {
        int m = k * TPB + tid;
#pragma unroll
        for (int c = 0; c < 3; c++) {
            A[3 * k + c]  = sbuf[3 * m + c];
            Bv[3 * k + c] = sbuf[IN_WORDS + 3 * m + c];
        }
    }
    __syncthreads();   // inputs now in regs; sbuf becomes output buffer

    // ---- Phase 3: compute, immediate stride-9 scalar STS (conflict-free) ----
#pragma unroll
    for (int k = 0; k < 2; k++) {
        float ax = A[3 * k + 0], ay = A[3 * k + 1], az = A[3 * k + 2];
        float bx = Bv[3 * k + 0], by = Bv[3 * k + 1], bz = Bv[3 * k + 2];

        float ra = rsqrtf(ax * ax + ay * ay + az * az);
        ax *= ra; ay *= ra; az *= ra;
        float rb = rsqrtf(bx * bx + by * by + bz * bz);
        bx *= rb; by *= rb; bz *= rb;

        // v = a x b
        float vx = ay * bz - az * by;
        float vy = az * bx - ax * bz;
        float vz = ax * by - ay * bx;
        float c  = ax * bx + ay * by + az * bz;
        float s2 = vx * vx + vy * vy + vz * vz;

        float coef = (1.0f - c) / (s2 > 0.0f ? s2 : 1.0f);

        // R = I + K + (v v^T - s2 I) * coef
        float r00 = 1.0f + (vx * vx - s2) * coef;
        float r01 = vx * vy * coef - vz;
        float r02 = vx * vz * coef + vy;
        float r10 = vx * vy * coef + vz;
        float r11 = 1.0f + (vy * vy - s2) * coef;
        float r12 = vy * vz * coef - vx;
        float r20 = vx * vz * coef - vy;
        float r21 = vy * vz * coef + vx;
        float r22 = 1.0f + (vz * vz - s2) * coef;

        float s = sqrtf(s2);
        if (s < S_EPS) {
            if (c > 0.0f) {
                r00 = 1.0f; r01 = 0.0f; r02 = 0.0f;
                r10 = 0.0f; r11 = 1.0f; r12 = 0.0f;
                r20 = 0.0f; r21 = 0.0f; r22 = 1.0f;
            } else if (c < 0.0f) {
                bool close_e1 = (fabsf(ax - 1.0f) <= ATOL_ + RTOL_) &&
                                (fabsf(ay) <= ATOL_) &&
                                (fabsf(az) <= ATOL_);
                float ex = close_e1 ? 0.0f : 1.0f;
                float ey = close_e1 ? 1.0f : 0.0f;
                float px = -az * ey;
                float py =  az * ex;
                float pz = ax * ey - ay * ex;
                float pn = sqrtf(px * px + py * py + pz * pz);
                float inv = (pn > 0.0f) ? (1.0f / pn) : 1.0f;
                px *= inv; py *= inv; pz *= inv;
                r00 = 2.0f * px * px - 1.0f;
                r01 = 2.0f * px * py;
                r02 = 2.0f * px * pz;
                r10 = 2.0f * py * px;
                r11 = 2.0f * py * py - 1.0f;
                r12 = 2.0f * py * pz;
                r20 = 2.0f * pz * px;
                r21 = 2.0f * pz * py;
                r22 = 2.0f * pz * pz - 1.0f;
            }
        }

        float* o = sbuf + 9 * (k * TPB + tid);
        o[0] = r00; o[1] = r01; o[2] = r02;
        o[3] = r10; o[4] = r11; o[5] = r12;
        o[6] = r20; o[7] = r21; o[8] = r22;
    }
    __syncthreads();

    // ---- Phase 4: coalesced streaming stores (evict-first) ----
    float4* dst = gout + (size_t)blk * OUT_F4;
#pragma unroll
    for (int j = 0; j < 4; j++)
        stg_streaming(dst + j * TPB + tid, sb4[j * TPB + tid]);
    if (tid < OUT_F4 - 4 * TPB)                      // 128, warp-uniform
        stg_streaming(dst + 4 * TPB + tid, sb4[4 * TPB + tid]);
}

extern "C" void kernel_launch(void* const* d_in, const int* in_sizes, int n_in,
                              void* d_out, int out_size)
{
    const float4* v1 = (const float4*)d_in[0];
    const float4* v2 = (const float4*)d_in[1];
    float4* out = (float4*)d_out;

    int n_elems = in_sizes[0] / 3;        // 4,194,304
    int blocks = n_elems / EPB;           // 8192 (exact)

    rodrigues_kernel<<<blocks, TPB>>>(v1, v2, out);
}

// round 16
// speedup vs baseline: 1.2549x; 1.0151x over previous
#include <cuda_runtime.h>
#include <cstdint>

// Rodrigues rotation matrix from two vectors — warp-synchronous version.
// TPB=256 (8 warps), 512 elems/block, 2 elems/thread. Each warp owns a
// contiguous 64-element slice: its input f4 range, smem regions and output
// f4 range are warp-private, so ALL cross-phase dependencies are intra-warp
// and both block barriers become __syncwarp(). 8 independent warp pipelines
// per CTA overlap load latency, compute and store drain.
// Loads carry L2 evict_last hint; stores are streaming (.cs).

#define S_EPS 1e-30f
#define RTOL_ 1e-5f
#define ATOL_ 1e-8f

#define TPB 256
#define EPB 512
#define IN_WORDS (EPB * 3)            // 1536 floats per input
#define OUT_WORDS (EPB * 9)           // 4608 floats = 18 KB
#define IN_F4 (IN_WORDS / 4)          // 384 f4 per input
#define OUT_F4 (OUT_WORDS / 4)        // 1152 f4
#define W_IN_F4 48                    // f4 per warp per input (64 elems * 3 / 4)
#define W_OUT_F4 144                  // f4 per warp out (64 elems * 9 / 4)

__device__ __forceinline__ float4 ldg_evict_last(const float4* p, uint64_t pol) {
    float4 v;
    asm volatile("ld.global.nc.L2::cache_hint.v4.f32 {%0,%1,%2,%3}, [%4], %5;"
                 : "=f"(v.x), "=f"(v.y), "=f"(v.z), "=f"(v.w)
                 : "l"(p), "l"(pol));
    return v;
}

__device__ __forceinline__ void stg_streaming(float4* p, float4 v) {
    asm volatile("st.global.cs.v4.f32 [%0], {%1,%2,%3,%4};"
                 :: "l"(p), "f"(v.x), "f"(v.y), "f"(v.z), "f"(v.w) : "memory");
}

__global__ __launch_bounds__(TPB, 6) void rodrigues_kernel(
    const float4* __restrict__ g1,
    const float4* __restrict__ g2,
    float4* __restrict__ gout)
{
    __shared__ float s_in[2 * IN_WORDS];   // 6 KB
    __shared__ float s_out[OUT_WORDS];     // 18 KB
    float4* si4 = (float4*)s_in;
    float4* so4 = (float4*)s_out;

    const int tid  = threadIdx.x;
    const int lane = tid & 31;
    const int w    = tid >> 5;             // warp id, 0..7
    const int blk  = blockIdx.x;

    uint64_t pol;
    asm volatile("createpolicy.fractional.L2::evict_last.b64 %0, 1.0;" : "=l"(pol));

    // ---- Phase 1: warp-private coalesced f4 loads -> smem ----
    // warp w: in1 f4 [w*48, w*48+48) -> si4[w*48 ...]
    //         in2 f4 [w*48, w*48+48) -> si4[IN_F4 + w*48 ...]
    const float4* in1 = g1 + (size_t)blk * IN_F4 + w * W_IN_F4;
    const float4* in2 = g2 + (size_t)blk * IN_F4 + w * W_IN_F4;
#pragma unroll
    for (int j = 0; j < 3; j++) {
        int i = j * 32 + lane;              // 0..95
        float4 v = (i < W_IN_F4) ? ldg_evict_last(in1 + i, pol)
                                 : ldg_evict_last(in2 + (i - W_IN_F4), pol);
        int d = (i < W_IN_F4) ? (w * W_IN_F4 + i)
                              : (IN_F4 + w * W_IN_F4 + (i - W_IN_F4));
        si4[d] = v;
    }
    __syncwarp();

    // ---- Phase 2: stride-3 scalar LDS (conflict-free) into regs ----
    // warp w's elements: m = w*64 + lane and w*64 + 32 + lane
    float A[6], Bv[6];
#pragma unroll
    for (int k = 0; k < 2; k++) {
        int m = w * 64 + k * 32 + lane;
#pragma unroll
        for (int c = 0; c < 3; c++) {
            A[3 * k + c]  = s_in[3 * m + c];
            Bv[3 * k + c] = s_in[IN_WORDS + 3 * m + c];
        }
    }

    // ---- Phase 3: compute, stride-9 scalar STS (conflict-free) ----
#pragma unroll
    for (int k = 0; k < 2; k++) {
        float ax = A[3 * k + 0], ay = A[3 * k + 1], az = A[3 * k + 2];
        float bx = Bv[3 * k + 0], by = Bv[3 * k + 1], bz = Bv[3 * k + 2];

        float ra = rsqrtf(ax * ax + ay * ay + az * az);
        ax *= ra; ay *= ra; az *= ra;
        float rb = rsqrtf(bx * bx + by * by + bz * bz);
        bx *= rb; by *= rb; bz *= rb;

        // v = a x b
        float vx = ay * bz - az * by;
        float vy = az * bx - ax * bz;
        float vz = ax * by - ay * bx;
        float c  = ax * bx + ay * by + az * bz;
        float s2 = vx * vx + vy * vy + vz * vz;

        float coef = (1.0f - c) / (s2 > 0.0f ? s2 : 1.0f);

        // R = I + K + (v v^T - s2 I) * coef
        float r00 = 1.0f + (vx * vx - s2) * coef;
        float r01 = vx * vy * coef - vz;
        float r02 = vx * vz * coef + vy;
        float r10 = vx * vy * coef + vz;
        float r11 = 1.0f + (vy * vy - s2) * coef;
        float r12 = vy * vz * coef - vx;
        float r20 = vx * vz * coef - vy;
        float r21 = vy * vz * coef + vx;
        float r22 = 1.0f + (vz * vz - s2) * coef;

        float s = sqrtf(s2);
        if (s < S_EPS) {
            if (c > 0.0f) {
                r00 = 1.0f; r01 = 0.0f; r02 = 0.0f;
                r10 = 0.0f; r11 = 1.0f; r12 = 0.0f;
                r20 = 0.0f; r21 = 0.0f; r22 = 1.0f;
            } else if (c < 0.0f) {
                bool close_e1 = (fabsf(ax - 1.0f) <= ATOL_ + RTOL_) &&
                                (fabsf(ay) <= ATOL_) &&
                                (fabsf(az) <= ATOL_);
                float ex = close_e1 ? 0.0f : 1.0f;
                float ey = close_e1 ? 1.0f : 0.0f;
                float px = -az * ey;
                float py =  az * ex;
                float pz = ax * ey - ay * ex;
                float pn = sqrtf(px * px + py * py + pz * pz);
                float inv = (pn > 0.0f) ? (1.0f / pn) : 1.0f;
                px *= inv; py *= inv; pz *= inv;
                r00 = 2.0f * px * px - 1.0f;
                r01 = 2.0f * px * py;
                r02 = 2.0f * px * pz;
                r10 = 2.0f * py * px;
                r11 = 2.0f * py * py - 1.0f;
                r12 = 2.0f * py * pz;
                r20 = 2.0f * pz * px;
                r21 = 2.0f * pz * py;
                r22 = 2.0f * pz * pz - 1.0f;
            }
        }

        int m = w * 64 + k * 32 + lane;
        float* o = s_out + 9 * m;
        o[0] = r00; o[1] = r01; o[2] = r02;
        o[3] = r10; o[4] = r11; o[5] = r12;
        o[6] = r20; o[7] = r21; o[8] = r22;
    }
    __syncwarp();

    // ---- Phase 4: warp-private coalesced streaming stores ----
    // warp w stores f4 [w*144, (w+1)*144)
    float4* dst = gout + (size_t)blk * OUT_F4 + w * W_OUT_F4;
    const float4* src = so4 + w * W_OUT_F4;
#pragma unroll
    for (int j = 0; j < 4; j++)
        stg_streaming(dst + j * 32 + lane, src[j * 32 + lane]);
    if (lane < W_OUT_F4 - 128)                       // 16 lanes
        stg_streaming(dst + 128 + lane, src[128 + lane]);
}

extern "C" void kernel_launch(void* const* d_in, const int* in_sizes, int n_in,
                              void* d_out, int out_size)
{
    const float4* v1 = (const float4*)d_in[0];
    const float4* v2 = (const float4*)d_in[1];
    float4* out = (float4*)d_out;

    int n_elems = in_sizes[0] / 3;        // 4,194,304
    int blocks = n_elems / EPB;           // 8192 (exact)

    rodrigues_kernel<<<blocks, TPB>>>(v1, v2, out);
}

// round 17
// speedup vs baseline: 1.2849x; 1.0239x over previous
#include <cuda_runtime.h>
#include <cstdint>

// Rodrigues rotation matrix from two vectors — warp-synchronous, aliased smem.
// TPB=256 (8 warps), 512 elems/block, 2 elems/thread, warp-private 64-elem
// slices: all cross-phase deps are intra-warp (__syncwarp only).
// Single 18KB smem buffer: warp w's 576-word output region also hosts its
// 384-word input staging (read into regs before output STS overwrites).
// 7 CTAs/SM via launch_bounds. Evict-last loads, streaming stores.

#define S_EPS 1e-30f
#define RTOL_ 1e-5f
#define ATOL_ 1e-8f

#define TPB 256
#define EPB 512
#define IN_F4_BLK (EPB * 3 / 4)       // 384 f4 per input per block
#define OUT_WORDS (EPB * 9)           // 4608 floats = 18 KB
#define OUT_F4 (OUT_WORDS / 4)        // 1152 f4
#define W_IN_F4 48                    // f4 per warp per input
#define W_OUT_F4 144                  // f4 per warp out
#define W_WORDS 576                   // words per warp region (= 144 f4)

__device__ __forceinline__ float4 ldg_evict_last(const float4* p, uint64_t pol) {
    float4 v;
    asm volatile("ld.global.nc.L2::cache_hint.v4.f32 {%0,%1,%2,%3}, [%4], %5;"
                 : "=f"(v.x), "=f"(v.y), "=f"(v.z), "=f"(v.w)
                 : "l"(p), "l"(pol));
    return v;
}

__device__ __forceinline__ void stg_streaming(float4* p, float4 v) {
    asm volatile("st.global.cs.v4.f32 [%0], {%1,%2,%3,%4};"
                 :: "l"(p), "f"(v.x), "f"(v.y), "f"(v.z), "f"(v.w) : "memory");
}

__global__ __launch_bounds__(TPB, 7) void rodrigues_kernel(
    const float4* __restrict__ g1,
    const float4* __restrict__ g2,
    float4* __restrict__ gout)
{
    __shared__ float sbuf[OUT_WORDS];      // 18 KB, per-warp regions, reused
    float4* sb4 = (float4*)sbuf;

    const int tid  = threadIdx.x;
    const int lane = tid & 31;
    const int w    = tid >> 5;             // warp id, 0..7
    const int blk  = blockIdx.x;

    // Warp-private region: words [w*576, (w+1)*576), f4 [w*144, (w+1)*144)
    float*  wbase  = sbuf + w * W_WORDS;
    float4* wbase4 = sb4 + w * W_OUT_F4;

    uint64_t pol;
    asm volatile("createpolicy.fractional.L2::evict_last.b64 %0, 1.0;" : "=l"(pol));

    // ---- Phase 1: warp-private coalesced f4 loads -> own region ----
    // in1 f4 -> wbase4[0..48), in2 f4 -> wbase4[48..96)
    const float4* in1 = g1 + (size_t)blk * IN_F4_BLK + w * W_IN_F4;
    const float4* in2 = g2 + (size_t)blk * IN_F4_BLK + w * W_IN_F4;
#pragma unroll
    for (int j = 0; j < 3; j++) {
        int i = j * 32 + lane;              // 0..95
        float4 v = (i < W_IN_F4) ? ldg_evict_last(in1 + i, pol)
                                 : ldg_evict_last(in2 + (i - W_IN_F4), pol);
        wbase4[i] = v;
    }
    __syncwarp();

    // ---- Phase 2: stride-3 scalar LDS (conflict-free) into regs ----
    // local element e = k*32 + lane (0..63); in1 words at wbase[3e],
    // in2 words at wbase[192*... ] -> in2 base = 192 f4*4 = wbase + 192 words? 
    // in2 occupies f4 [48..96) = words [192, 384).
    float A[6], Bv[6];
#pragma unroll
    for (int k = 0; k < 2; k++) {
        int e = k * 32 + lane;
#pragma unroll
        for (int c = 0; c < 3; c++) {
            A[3 * k + c]  = wbase[3 * e + c];
            Bv[3 * k + c] = wbase[192 + 3 * e + c];
        }
    }
    __syncwarp();   // all lanes done reading; region becomes output buffer

    // ---- Phase 3: compute, stride-9 scalar STS (conflict-free) ----
#pragma unroll
    for (int k = 0; k < 2; k++) {
        float ax = A[3 * k + 0], ay = A[3 * k + 1], az = A[3 * k + 2];
        float bx = Bv[3 * k + 0], by = Bv[3 * k + 1], bz = Bv[3 * k + 2];

        float ra = rsqrtf(ax * ax + ay * ay + az * az);
        ax *= ra; ay *= ra; az *= ra;
        float rb = rsqrtf(bx * bx + by * by + bz * bz);
        bx *= rb; by *= rb; bz *= rb;

        // v = a x b
        float vx = ay * bz - az * by;
        float vy = az * bx - ax * bz;
        float vz = ax * by - ay * bx;
        float c  = ax * bx + ay * by + az * bz;
        float s2 = vx * vx + vy * vy + vz * vz;

        float coef = (1.0f - c) / (s2 > 0.0f ? s2 : 1.0f);

        // R = I + K + (v v^T - s2 I) * coef
        float r00 = 1.0f + (vx * vx - s2) * coef;
        float r01 = vx * vy * coef - vz;
        float r02 = vx * vz * coef + vy;
        float r10 = vx * vy * coef + vz;
        float r11 = 1.0f + (vy * vy - s2) * coef;
        float r12 = vy * vz * coef - vx;
        float r20 = vx * vz * coef - vy;
        float r21 = vy * vz * coef + vx;
        float r22 = 1.0f + (vz * vz - s2) * coef;

        float s = sqrtf(s2);
        if (s < S_EPS) {
            if (c > 0.0f) {
                r00 = 1.0f; r01 = 0.0f; r02 = 0.0f;
                r10 = 0.0f; r11 = 1.0f; r12 = 0.0f;
                r20 = 0.0f; r21 = 0.0f; r22 = 1.0f;
            } else if (c < 0.0f) {
                bool close_e1 = (fabsf(ax - 1.0f) <= ATOL_ + RTOL_) &&
                                (fabsf(ay) <= ATOL_) &&
                                (fabsf(az) <= ATOL_);
                float ex = close_e1 ? 0.0f : 1.0f;
                float ey = close_e1 ? 1.0f : 0.0f;
                float px = -az * ey;
                float py =  az * ex;
                float pz = ax * ey - ay * ex;
                float pn = sqrtf(px * px + py * py + pz * pz);
                float inv = (pn > 0.0f) ? (1.0f / pn) : 1.0f;
                px *= inv; py *= inv; pz *= inv;
                r00 = 2.0f * px * px - 1.0f;
                r01 = 2.0f * px * py;
                r02 = 2.0f * px * pz;
                r10 = 2.0f * py * px;
                r11 = 2.0f * py * py - 1.0f;
                r12 = 2.0f * py * pz;
                r20 = 2.0f * pz * px;
                r21 = 2.0f * pz * py;
                r22 = 2.0f * pz * pz - 1.0f;
            }
        }

        int e = k * 32 + lane;
        float* o = wbase + 9 * e;
        o[0] = r00; o[1] = r01; o[2] = r02;
        o[3] = r10; o[4] = r11; o[5] = r12;
        o[6] = r20; o[7] = r21; o[8] = r22;
    }
    __syncwarp();

    // ---- Phase 4: warp-private coalesced streaming stores ----
    float4* dst = gout + (size_t)blk * OUT_F4 + w * W_OUT_F4;
#pragma unroll
    for (int j = 0; j < 4; j++)
        stg_streaming(dst + j * 32 + lane, wbase4[j * 32 + lane]);
    if (lane < W_OUT_F4 - 128)                       // 16 lanes
        stg_streaming(dst + 128 + lane, wbase4[128 + lane]);
}

extern "C" void kernel_launch(void* const* d_in, const int* in_sizes, int n_in,
                              void* d_out, int out_size)
{
    const float4* v1 = (const float4*)d_in[0];
    const float4* v2 = (const float4*)d_in[1];
    float4* out = (float4*)d_out;

    int n_elems = in_sizes[0] / 3;        // 4,194,304
    int blocks = n_elems / EPB;           // 8192 (exact)

    rodrigues_kernel<<<blocks, TPB>>>(v1, v2, out);
}